// round 1
// baseline (speedup 1.0000x reference)
#include <cuda_runtime.h>
#include <math.h>

#define TPB 256
#define MAX_BLOCKS 2048
#define ANGW 0.1f
#define RAD2DEG 57.29577951308232f

__device__ float g_pch[MAX_BLOCKS];
__device__ float g_pang[MAX_BLOCKS];

// Eigenvector of symmetric A for eigenvalue lam via largest cross product of rows of (A - lam I).
__device__ __forceinline__ void eigvec3(
    float a00, float a01, float a02, float a11, float a12, float a22,
    float lam, float v[3])
{
    float r0x = a00 - lam, r0y = a01,       r0z = a02;
    float r1x = a01,       r1y = a11 - lam, r1z = a12;
    float r2x = a02,       r2y = a12,       r2z = a22 - lam;

    float c0x = r0y*r1z - r0z*r1y, c0y = r0z*r1x - r0x*r1z, c0z = r0x*r1y - r0y*r1x;
    float c1x = r0y*r2z - r0z*r2y, c1y = r0z*r2x - r0x*r2z, c1z = r0x*r2y - r0y*r2x;
    float c2x = r1y*r2z - r1z*r2y, c2y = r1z*r2x - r1x*r2z, c2z = r1x*r2y - r1y*r2x;

    float n0 = c0x*c0x + c0y*c0y + c0z*c0z;
    float n1 = c1x*c1x + c1y*c1y + c1z*c1z;
    float n2 = c2x*c2x + c2y*c2y + c2z*c2z;

    float bx = c0x, by = c0y, bz = c0z, bn = n0;
    if (n1 > bn) { bx = c1x; by = c1y; bz = c1z; bn = n1; }
    if (n2 > bn) { bx = c2x; by = c2y; bz = c2z; bn = n2; }
    if (bn < 1e-30f) { v[0] = 1.f; v[1] = 0.f; v[2] = 0.f; return; }
    float inv = rsqrtf(bn);
    v[0] = bx*inv; v[1] = by*inv; v[2] = bz*inv;
}

// Nearest rotation (special-orthogonal Procrustes) to 3x3 row-major M.
__device__ __forceinline__ void nearest_rotation(const float M[9], float R[9])
{
    // A = M^T M (symmetric PSD)
    float a00 = M[0]*M[0] + M[3]*M[3] + M[6]*M[6];
    float a11 = M[1]*M[1] + M[4]*M[4] + M[7]*M[7];
    float a22 = M[2]*M[2] + M[5]*M[5] + M[8]*M[8];
    float a01 = M[0]*M[1] + M[3]*M[4] + M[6]*M[7];
    float a02 = M[0]*M[2] + M[3]*M[5] + M[6]*M[8];
    float a12 = M[1]*M[2] + M[4]*M[5] + M[7]*M[8];

    // Cardano eigenvalues (lam1 >= lam2 >= lam3)
    float q   = (a00 + a11 + a22) * (1.0f/3.0f);
    float b00 = a00 - q, b11 = a11 - q, b22 = a22 - q;
    float p2  = b00*b00 + b11*b11 + b22*b22
              + 2.0f*(a01*a01 + a02*a02 + a12*a12);
    float lam1 = q, lam3 = q;
    if (p2 > 1e-24f) {
        float p  = sqrtf(p2 * (1.0f/6.0f));
        float ip = 1.0f / p;
        float det = b00*(b11*b22 - a12*a12)
                  - a01*(a01*b22 - a12*a02)
                  + a02*(a01*a12 - b11*a02);
        float rr = 0.5f * det * ip * ip * ip;
        rr = fminf(1.0f, fmaxf(-1.0f, rr));
        float phi = acosf(rr) * (1.0f/3.0f);   // phi in [0, pi/3]
        float s, c;
        __sincosf(phi, &s, &c);
        lam1 = q + 2.0f*p*c;
        lam3 = q + p*(-c - 1.7320508075688772f*s);
    }

    // v1: eigvec for largest, v3: eigvec for smallest (both extremes -> well conditioned)
    float v1[3], v3[3];
    eigvec3(a00, a01, a02, a11, a12, a22, lam1, v1);
    eigvec3(a00, a01, a02, a11, a12, a22, lam3, v3);

    // Orthogonalize v3 against v1 (exactly orthogonal in exact arithmetic)
    float d = v3[0]*v1[0] + v3[1]*v1[1] + v3[2]*v1[2];
    v3[0] -= d*v1[0]; v3[1] -= d*v1[1]; v3[2] -= d*v1[2];
    float n = v3[0]*v3[0] + v3[1]*v3[1] + v3[2]*v3[2];
    if (n < 1e-12f) {
        // degenerate: pick axis least aligned with v1
        float ax = fabsf(v1[0]), ay = fabsf(v1[1]), az = fabsf(v1[2]);
        float ex = (ax <= ay && ax <= az) ? 1.f : 0.f;
        float ey = (ex == 0.f && ay <= az) ? 1.f : 0.f;
        float ez = 1.f - ex - ey;
        v3[0] = v1[1]*ez - v1[2]*ey;
        v3[1] = v1[2]*ex - v1[0]*ez;
        v3[2] = v1[0]*ey - v1[1]*ex;
        n = v3[0]*v3[0] + v3[1]*v3[1] + v3[2]*v3[2];
    }
    float inv = rsqrtf(n);
    v3[0] *= inv; v3[1] *= inv; v3[2] *= inv;

    // v2 = v3 x v1  -> V = [v1 v2 v3] is right-handed (det +1)
    float v2[3] = { v3[1]*v1[2] - v3[2]*v1[1],
                    v3[2]*v1[0] - v3[0]*v1[2],
                    v3[0]*v1[1] - v3[1]*v1[0] };

    // u1 = normalize(M v1)
    float u1[3], u2[3], u3[3];
    u1[0] = M[0]*v1[0] + M[1]*v1[1] + M[2]*v1[2];
    u1[1] = M[3]*v1[0] + M[4]*v1[1] + M[5]*v1[2];
    u1[2] = M[6]*v1[0] + M[7]*v1[1] + M[8]*v1[2];
    n = u1[0]*u1[0] + u1[1]*u1[1] + u1[2]*u1[2];
    if (n < 1e-30f) { u1[0] = 1.f; u1[1] = 0.f; u1[2] = 0.f; }
    else { inv = rsqrtf(n); u1[0] *= inv; u1[1] *= inv; u1[2] *= inv; }

    // u2 = Gram-Schmidt(M v2, u1)
    u2[0] = M[0]*v2[0] + M[1]*v2[1] + M[2]*v2[2];
    u2[1] = M[3]*v2[0] + M[4]*v2[1] + M[5]*v2[2];
    u2[2] = M[6]*v2[0] + M[7]*v2[1] + M[8]*v2[2];
    d = u2[0]*u1[0] + u2[1]*u1[1] + u2[2]*u1[2];
    u2[0] -= d*u1[0]; u2[1] -= d*u1[1]; u2[2] -= d*u1[2];
    n = u2[0]*u2[0] + u2[1]*u2[1] + u2[2]*u2[2];
    if (n < 1e-20f) {
        float ax = fabsf(u1[0]), ay = fabsf(u1[1]), az = fabsf(u1[2]);
        float ex = (ax <= ay && ax <= az) ? 1.f : 0.f;
        float ey = (ex == 0.f && ay <= az) ? 1.f : 0.f;
        float ez = 1.f - ex - ey;
        u2[0] = u1[1]*ez - u1[2]*ey;
        u2[1] = u1[2]*ex - u1[0]*ez;
        u2[2] = u1[0]*ey - u1[1]*ex;
        n = u2[0]*u2[0] + u2[1]*u2[1] + u2[2]*u2[2];
    }
    inv = rsqrtf(n);
    u2[0] *= inv; u2[1] *= inv; u2[2] *= inv;

    // u3 = u1 x u2 : forces det(U)=+1 == the SVD det-correction (flip of smallest-sv column)
    u3[0] = u1[1]*u2[2] - u1[2]*u2[1];
    u3[1] = u1[2]*u2[0] - u1[0]*u2[2];
    u3[2] = u1[0]*u2[1] - u1[1]*u2[0];

    // R = U V^T = u1 v1^T + u2 v2^T + u3 v3^T
    #pragma unroll
    for (int i = 0; i < 3; i++) {
        float a = u1[i], b = u2[i], c = u3[i];
        R[3*i+0] = a*v1[0] + b*v2[0] + c*v3[0];
        R[3*i+1] = a*v1[1] + b*v2[1] + c*v3[1];
        R[3*i+2] = a*v1[2] + b*v2[2] + c*v3[2];
    }
}

__global__ void __launch_bounds__(TPB)
rotloss_kernel(const float* __restrict__ pred, const float* __restrict__ target, int B)
{
    float ch = 0.f, ang = 0.f;
    for (int i = blockIdx.x * blockDim.x + threadIdx.x; i < B;
         i += gridDim.x * blockDim.x) {
        float P[9], T[9], Rp[9], Rt[9];
        #pragma unroll
        for (int k = 0; k < 9; k++) P[k] = pred[9*i + k];
        #pragma unroll
        for (int k = 0; k < 9; k++) T[k] = target[9*i + k];

        nearest_rotation(P, Rp);
        nearest_rotation(T, Rt);

        float d2 = 0.f, tr = 0.f;
        #pragma unroll
        for (int k = 0; k < 9; k++) {
            float dd = Rp[k] - Rt[k];
            d2 += dd * dd;
            tr += Rp[k] * Rt[k];
        }
        ch += d2;
        float ct = (tr - 1.0f) * 0.5f;
        ct = fminf(1.0f - 1e-7f, fmaxf(-1.0f + 1e-7f, ct));
        ang += acosf(ct) * RAD2DEG;
    }

    // warp reduce
    #pragma unroll
    for (int off = 16; off; off >>= 1) {
        ch  += __shfl_down_sync(0xffffffffu, ch,  off);
        ang += __shfl_down_sync(0xffffffffu, ang, off);
    }
    __shared__ float sch[TPB/32], sang[TPB/32];
    int w = threadIdx.x >> 5, l = threadIdx.x & 31;
    if (l == 0) { sch[w] = ch; sang[w] = ang; }
    __syncthreads();
    if (threadIdx.x == 0) {
        float c2 = 0.f, a2 = 0.f;
        #pragma unroll
        for (int j = 0; j < TPB/32; j++) { c2 += sch[j]; a2 += sang[j]; }
        g_pch[blockIdx.x]  = c2;
        g_pang[blockIdx.x] = a2;
    }
}

__global__ void __launch_bounds__(TPB)
finalize_kernel(float* __restrict__ out, int nblocks, float invB)
{
    float ch = 0.f, ang = 0.f;
    for (int j = threadIdx.x; j < nblocks; j += TPB) {
        ch  += g_pch[j];
        ang += g_pang[j];
    }
    #pragma unroll
    for (int off = 16; off; off >>= 1) {
        ch  += __shfl_down_sync(0xffffffffu, ch,  off);
        ang += __shfl_down_sync(0xffffffffu, ang, off);
    }
    __shared__ float sch[TPB/32], sang[TPB/32];
    int w = threadIdx.x >> 5, l = threadIdx.x & 31;
    if (l == 0) { sch[w] = ch; sang[w] = ang; }
    __syncthreads();
    if (threadIdx.x == 0) {
        float c2 = 0.f, a2 = 0.f;
        #pragma unroll
        for (int j = 0; j < TPB/32; j++) { c2 += sch[j]; a2 += sang[j]; }
        out[0] = (c2 + ANGW * a2) * invB;
    }
}

extern "C" void kernel_launch(void* const* d_in, const int* in_sizes, int n_in,
                              void* d_out, int out_size)
{
    const float* pred   = (const float*)d_in[0];
    const float* target = (const float*)d_in[1];
    float* out = (float*)d_out;

    int B = in_sizes[0] / 9;
    int blocks = (B + TPB - 1) / TPB;
    if (blocks > MAX_BLOCKS) blocks = MAX_BLOCKS;
    if (blocks < 1) blocks = 1;

    rotloss_kernel<<<blocks, TPB>>>(pred, target, B);
    finalize_kernel<<<1, TPB>>>(out, blocks, 1.0f / (float)B);
}

// round 2
// speedup vs baseline: 1.1064x; 1.1064x over previous
#include <cuda_runtime.h>
#include <math.h>

#define TPB 256
#define MAX_BLOCKS 2048
#define ANGW 0.1f
#define RAD2DEG 57.29577951308232f
#define PI_F 3.14159265358979f

__device__ float g_ptr_[MAX_BLOCKS];   // partial trace sums
__device__ float g_pang[MAX_BLOCKS];   // partial angular sums
__device__ unsigned int g_count = 0;

// Fast acos: Abramowitz-Stegun 4.4.45, max abs err ~6.7e-5 rad.
__device__ __forceinline__ float fast_acos(float x)
{
    float ax = fabsf(x);
    float p = fmaf(ax, -0.0187293f, 0.0742610f);
    p = fmaf(p, ax, -0.2121144f);
    p = fmaf(p, ax, 1.5707288f);
    float s = fmaxf(1.0f - ax, 1e-30f);
    float r = s * rsqrtf(s) * p;           // sqrt(s)*p without full sqrt
    return (x >= 0.f) ? r : PI_F - r;
}

// Eigenvector of symmetric A for eigenvalue lam via largest cross product of rows of (A - lam I).
__device__ __forceinline__ void eigvec3(
    float a00, float a01, float a02, float a11, float a12, float a22,
    float lam, float v[3])
{
    float r0x = a00 - lam, r0y = a01,       r0z = a02;
    float r1x = a01,       r1y = a11 - lam, r1z = a12;
    float r2x = a02,       r2y = a12,       r2z = a22 - lam;

    float c0x = r0y*r1z - r0z*r1y, c0y = r0z*r1x - r0x*r1z, c0z = r0x*r1y - r0y*r1x;
    float c1x = r0y*r2z - r0z*r2y, c1y = r0z*r2x - r0x*r2z, c1z = r0x*r2y - r0y*r2x;
    float c2x = r1y*r2z - r1z*r2y, c2y = r1z*r2x - r1x*r2z, c2z = r1x*r2y - r1y*r2x;

    float n0 = c0x*c0x + c0y*c0y + c0z*c0z;
    float n1 = c1x*c1x + c1y*c1y + c1z*c1z;
    float n2 = c2x*c2x + c2y*c2y + c2z*c2z;

    float bx = c0x, by = c0y, bz = c0z, bn = n0;
    if (n1 > bn) { bx = c1x; by = c1y; bz = c1z; bn = n1; }
    if (n2 > bn) { bx = c2x; by = c2y; bz = c2z; bn = n2; }
    if (bn < 1e-30f) { v[0] = 1.f; v[1] = 0.f; v[2] = 0.f; return; }
    float inv = rsqrtf(bn);
    v[0] = bx*inv; v[1] = by*inv; v[2] = bz*inv;
}

// Nearest rotation (special-orthogonal Procrustes) to 3x3 row-major M.
__device__ __forceinline__ void nearest_rotation(const float M[9], float R[9])
{
    // A = M^T M (symmetric PSD)
    float a00 = M[0]*M[0] + M[3]*M[3] + M[6]*M[6];
    float a11 = M[1]*M[1] + M[4]*M[4] + M[7]*M[7];
    float a22 = M[2]*M[2] + M[5]*M[5] + M[8]*M[8];
    float a01 = M[0]*M[1] + M[3]*M[4] + M[6]*M[7];
    float a02 = M[0]*M[2] + M[3]*M[5] + M[6]*M[8];
    float a12 = M[1]*M[2] + M[4]*M[5] + M[7]*M[8];

    // Cardano eigenvalues (lam1 >= lam2 >= lam3), branch-free
    float q   = (a00 + a11 + a22) * (1.0f/3.0f);
    float b00 = a00 - q, b11 = a11 - q, b22 = a22 - q;
    float p2  = b00*b00 + b11*b11 + b22*b22
              + 2.0f*(a01*a01 + a02*a02 + a12*a12);
    float p2s = fmaxf(p2 * (1.0f/6.0f), 1e-30f);
    float ip  = rsqrtf(p2s);               // 1/p
    float p   = p2s * ip;                  // sqrt(p2/6)
    float det = b00*(b11*b22 - a12*a12)
              - a01*(a01*b22 - a12*a02)
              + a02*(a01*a12 - b11*a02);
    float rr = 0.5f * det * ip * ip * ip;
    rr = fminf(1.0f, fmaxf(-1.0f, rr));
    float phi = fast_acos(rr) * (1.0f/3.0f);   // phi in [0, pi/3]
    float s, c;
    __sincosf(phi, &s, &c);
    float lam1 = q + 2.0f*p*c;
    float lam3 = q + p*(-c - 1.7320508075688772f*s);

    // v1: eigvec for largest, v3: eigvec for smallest (both extremes -> well conditioned)
    float v1[3], v3[3];
    eigvec3(a00, a01, a02, a11, a12, a22, lam1, v1);
    eigvec3(a00, a01, a02, a11, a12, a22, lam3, v3);

    // Orthogonalize v3 against v1
    float d = v3[0]*v1[0] + v3[1]*v1[1] + v3[2]*v1[2];
    v3[0] -= d*v1[0]; v3[1] -= d*v1[1]; v3[2] -= d*v1[2];
    float n = v3[0]*v3[0] + v3[1]*v3[1] + v3[2]*v3[2];
    if (n < 1e-12f) {
        float ax = fabsf(v1[0]), ay = fabsf(v1[1]), az = fabsf(v1[2]);
        float ex = (ax <= ay && ax <= az) ? 1.f : 0.f;
        float ey = (ex == 0.f && ay <= az) ? 1.f : 0.f;
        float ez = 1.f - ex - ey;
        v3[0] = v1[1]*ez - v1[2]*ey;
        v3[1] = v1[2]*ex - v1[0]*ez;
        v3[2] = v1[0]*ey - v1[1]*ex;
        n = v3[0]*v3[0] + v3[1]*v3[1] + v3[2]*v3[2];
    }
    float inv = rsqrtf(n);
    v3[0] *= inv; v3[1] *= inv; v3[2] *= inv;

    // v2 = v3 x v1  -> V = [v1 v2 v3] right-handed
    float v2[3] = { v3[1]*v1[2] - v3[2]*v1[1],
                    v3[2]*v1[0] - v3[0]*v1[2],
                    v3[0]*v1[1] - v3[1]*v1[0] };

    // u1 = normalize(M v1)
    float u1[3], u2[3], u3[3];
    u1[0] = M[0]*v1[0] + M[1]*v1[1] + M[2]*v1[2];
    u1[1] = M[3]*v1[0] + M[4]*v1[1] + M[5]*v1[2];
    u1[2] = M[6]*v1[0] + M[7]*v1[1] + M[8]*v1[2];
    n = u1[0]*u1[0] + u1[1]*u1[1] + u1[2]*u1[2];
    if (n < 1e-30f) { u1[0] = 1.f; u1[1] = 0.f; u1[2] = 0.f; }
    else { inv = rsqrtf(n); u1[0] *= inv; u1[1] *= inv; u1[2] *= inv; }

    // u2 = Gram-Schmidt(M v2, u1)
    u2[0] = M[0]*v2[0] + M[1]*v2[1] + M[2]*v2[2];
    u2[1] = M[3]*v2[0] + M[4]*v2[1] + M[5]*v2[2];
    u2[2] = M[6]*v2[0] + M[7]*v2[1] + M[8]*v2[2];
    d = u2[0]*u1[0] + u2[1]*u1[1] + u2[2]*u1[2];
    u2[0] -= d*u1[0]; u2[1] -= d*u1[1]; u2[2] -= d*u1[2];
    n = u2[0]*u2[0] + u2[1]*u2[1] + u2[2]*u2[2];
    if (n < 1e-20f) {
        float ax = fabsf(u1[0]), ay = fabsf(u1[1]), az = fabsf(u1[2]);
        float ex = (ax <= ay && ax <= az) ? 1.f : 0.f;
        float ey = (ex == 0.f && ay <= az) ? 1.f : 0.f;
        float ez = 1.f - ex - ey;
        u2[0] = u1[1]*ez - u1[2]*ey;
        u2[1] = u1[2]*ex - u1[0]*ez;
        u2[2] = u1[0]*ey - u1[1]*ex;
        n = u2[0]*u2[0] + u2[1]*u2[1] + u2[2]*u2[2];
    }
    inv = rsqrtf(n);
    u2[0] *= inv; u2[1] *= inv; u2[2] *= inv;

    // u3 = u1 x u2 : forces det(U)=+1 == the SVD det-correction
    u3[0] = u1[1]*u2[2] - u1[2]*u2[1];
    u3[1] = u1[2]*u2[0] - u1[0]*u2[2];
    u3[2] = u1[0]*u2[1] - u1[1]*u2[0];

    // R = u1 v1^T + u2 v2^T + u3 v3^T
    #pragma unroll
    for (int i = 0; i < 3; i++) {
        float a = u1[i], b = u2[i], c2 = u3[i];
        R[3*i+0] = a*v1[0] + b*v2[0] + c2*v3[0];
        R[3*i+1] = a*v1[1] + b*v2[1] + c2*v3[1];
        R[3*i+2] = a*v1[2] + b*v2[2] + c2*v3[2];
    }
}

__global__ void __launch_bounds__(TPB)
rotloss_kernel(const float* __restrict__ pred, const float* __restrict__ target,
               float* __restrict__ out, int B, float invB)
{
    float trs = 0.f, ang = 0.f;
    for (int i = blockIdx.x * blockDim.x + threadIdx.x; i < B;
         i += gridDim.x * blockDim.x) {
        float P[9], T[9], Rp[9], Rt[9];
        #pragma unroll
        for (int k = 0; k < 9; k++) P[k] = pred[9*i + k];
        #pragma unroll
        for (int k = 0; k < 9; k++) T[k] = target[9*i + k];

        nearest_rotation(P, Rp);
        nearest_rotation(T, Rt);

        // chordal = 6 - 2*tr for rotations; only need the trace.
        float tr = 0.f;
        #pragma unroll
        for (int k = 0; k < 9; k++) tr = fmaf(Rp[k], Rt[k], tr);
        trs += tr;
        float ct = (tr - 1.0f) * 0.5f;
        ct = fminf(1.0f - 1e-7f, fmaxf(-1.0f + 1e-7f, ct));
        ang += fast_acos(ct) * RAD2DEG;
    }

    // warp reduce
    #pragma unroll
    for (int off = 16; off; off >>= 1) {
        trs += __shfl_down_sync(0xffffffffu, trs, off);
        ang += __shfl_down_sync(0xffffffffu, ang, off);
    }
    __shared__ float str[TPB/32], sang[TPB/32];
    int w = threadIdx.x >> 5, l = threadIdx.x & 31;
    if (l == 0) { str[w] = trs; sang[w] = ang; }
    __syncthreads();
    if (threadIdx.x == 0) {
        float t2 = 0.f, a2 = 0.f;
        #pragma unroll
        for (int j = 0; j < TPB/32; j++) { t2 += str[j]; a2 += sang[j]; }
        g_ptr_[blockIdx.x] = t2;
        g_pang[blockIdx.x] = a2;
    }

    // last-block finalize (self-resetting counter -> graph-replay safe)
    __threadfence();
    __shared__ bool isLast;
    if (threadIdx.x == 0) {
        unsigned int t = atomicAdd(&g_count, 1u);
        isLast = (t == gridDim.x - 1);
    }
    __syncthreads();
    if (!isLast) return;

    float t2 = 0.f, a2 = 0.f;
    for (int j = threadIdx.x; j < (int)gridDim.x; j += TPB) {
        t2 += g_ptr_[j];
        a2 += g_pang[j];
    }
    #pragma unroll
    for (int off = 16; off; off >>= 1) {
        t2 += __shfl_down_sync(0xffffffffu, t2, off);
        a2 += __shfl_down_sync(0xffffffffu, a2, off);
    }
    __shared__ float ftr[TPB/32], fang[TPB/32];
    if (l == 0) { ftr[w] = t2; fang[w] = a2; }
    __syncthreads();
    if (threadIdx.x == 0) {
        float tt = 0.f, aa = 0.f;
        #pragma unroll
        for (int j = 0; j < TPB/32; j++) { tt += ftr[j]; aa += fang[j]; }
        out[0] = fmaf(-2.0f * invB, tt, 6.0f) + ANGW * aa * invB;
        g_count = 0;   // reset for next graph replay
    }
}

extern "C" void kernel_launch(void* const* d_in, const int* in_sizes, int n_in,
                              void* d_out, int out_size)
{
    const float* pred   = (const float*)d_in[0];
    const float* target = (const float*)d_in[1];
    float* out = (float*)d_out;

    int B = in_sizes[0] / 9;
    int blocks = (B + TPB - 1) / TPB;
    if (blocks > MAX_BLOCKS) blocks = MAX_BLOCKS;
    if (blocks < 1) blocks = 1;

    rotloss_kernel<<<blocks, TPB>>>(pred, target, out, B, 1.0f / (float)B);
}